// round 7
// baseline (speedup 1.0000x reference)
#include <cuda_runtime.h>
#include <cstdint>

#define NQ     8
#define DIM    256
#define NW     16
#define BATCH  16
#define NROTS  64
#define EMB    512
#define VOCAB  50257
#define NM     24

typedef unsigned long long ull;

/* ---------------- scratch (device globals) ------------------------------- */
__device__ float  g_fp[BATCH];
__device__ float  g_h[BATCH * EMB];
__device__ float2 g_cs[BATCH * NW * NROTS];   /* cos/sin of wparams */

/* ---------------- packed f32x2 helpers ----------------------------------- */
__device__ __forceinline__ ull fma2(ull a, ull b, ull c) {
    ull d;
    asm("fma.rn.f32x2 %0, %1, %2, %3;" : "=l"(d) : "l"(a), "l"(b), "l"(c));
    return d;
}
__device__ __forceinline__ float2 upk2(ull v) {
    float lo, hi;
    asm("mov.b64 {%0, %1}, %2;" : "=f"(lo), "=f"(hi) : "l"(v));
    return make_float2(lo, hi);
}

/* ============ warp-level statevector gates (amp i = lane*8 + r) ==========
   bit 0..2 of i = register index r; bit 3..7 = lane bits 0..4.             */
__device__ __forceinline__ float2 shfl_xor_f2(float2 v, int m) {
    float2 r;
    r.x = __shfl_xor_sync(0xffffffffu, v.x, m);
    r.y = __shfl_xor_sync(0xffffffffu, v.y, m);
    return r;
}

template<int BP>
__device__ __forceinline__ void ry_reg(float2* v, float c, float s) {
#pragma unroll
    for (int r0 = 0; r0 < 8; r0++) {
        if (r0 & (1 << BP)) continue;
        const int r1 = r0 | (1 << BP);
        float2 a0 = v[r0], a1 = v[r1];
        v[r0] = make_float2(c * a0.x - s * a1.x, c * a0.y - s * a1.y);
        v[r1] = make_float2(s * a0.x + c * a1.x, s * a0.y + c * a1.y);
    }
}
template<int LB>
__device__ __forceinline__ void ry_lane(float2* v, float c, float s, int lane) {
    float ss = ((lane >> LB) & 1) ? s : -s;
#pragma unroll
    for (int r = 0; r < 8; r++) {
        float2 p = shfl_xor_f2(v[r], 1 << LB);
        v[r].x = c * v[r].x + ss * p.x;
        v[r].y = c * v[r].y + ss * p.y;
    }
}
template<int BC, int BT>
__device__ __forceinline__ void crx_rr(float2* v, float c, float s) {
#pragma unroll
    for (int r0 = 0; r0 < 8; r0++) {
        if (!(r0 & (1 << BC)) || (r0 & (1 << BT))) continue;
        const int r1 = r0 | (1 << BT);
        float2 a0 = v[r0], a1 = v[r1];
        v[r0] = make_float2(c * a0.x + s * a1.y, c * a0.y - s * a1.x);
        v[r1] = make_float2(s * a0.y + c * a1.x, -s * a0.x + c * a1.y);
    }
}
template<int LC, int BT>
__device__ __forceinline__ void crx_lr(float2* v, float c, float s, int lane) {
    if ((lane >> LC) & 1) {
#pragma unroll
        for (int r0 = 0; r0 < 8; r0++) {
            if (r0 & (1 << BT)) continue;
            const int r1 = r0 | (1 << BT);
            float2 a0 = v[r0], a1 = v[r1];
            v[r0] = make_float2(c * a0.x + s * a1.y, c * a0.y - s * a1.x);
            v[r1] = make_float2(s * a0.y + c * a1.x, -s * a0.x + c * a1.y);
        }
    }
}
template<int BC, int LT>
__device__ __forceinline__ void crx_rl(float2* v, float c, float s) {
#pragma unroll
    for (int r = 0; r < 8; r++) {
        if (!(r & (1 << BC))) continue;
        float2 p = shfl_xor_f2(v[r], 1 << LT);
        float2 a = v[r];
        v[r].x = c * a.x + s * p.y;
        v[r].y = c * a.y - s * p.x;
    }
}
template<int LC, int LT>
__device__ __forceinline__ void crx_ll(float2* v, float c, float s, int lane) {
    bool act = (lane >> LC) & 1;
#pragma unroll
    for (int r = 0; r < 8; r++) {
        float2 p = shfl_xor_f2(v[r], 1 << LT);
        if (act) {
            float2 a = v[r];
            v[r].x = c * a.x + s * p.y;
            v[r].y = c * a.y - s * p.x;
        }
    }
}

/* one 32-gate ansatz layer */
__device__ __forceinline__ void sim_layer(float2* v, const float2* cs, int lane) {
    float2 g;
    g = cs[0];  ry_lane<4>(v, g.x, g.y, lane);
    g = cs[1];  ry_lane<3>(v, g.x, g.y, lane);
    g = cs[2];  ry_lane<2>(v, g.x, g.y, lane);
    g = cs[3];  ry_lane<1>(v, g.x, g.y, lane);
    g = cs[4];  ry_lane<0>(v, g.x, g.y, lane);
    g = cs[5];  ry_reg<2>(v, g.x, g.y);
    g = cs[6];  ry_reg<1>(v, g.x, g.y);
    g = cs[7];  ry_reg<0>(v, g.x, g.y);
    g = cs[8];  crx_rl<0, 4>(v, g.x, g.y);
    g = cs[9];  crx_rr<1, 0>(v, g.x, g.y);
    g = cs[10]; crx_rr<2, 1>(v, g.x, g.y);
    g = cs[11]; crx_lr<0, 2>(v, g.x, g.y, lane);
    g = cs[12]; crx_ll<1, 0>(v, g.x, g.y, lane);
    g = cs[13]; crx_ll<2, 1>(v, g.x, g.y, lane);
    g = cs[14]; crx_ll<3, 2>(v, g.x, g.y, lane);
    g = cs[15]; crx_ll<4, 3>(v, g.x, g.y, lane);
    g = cs[16]; ry_lane<4>(v, g.x, g.y, lane);
    g = cs[17]; ry_lane<3>(v, g.x, g.y, lane);
    g = cs[18]; ry_lane<2>(v, g.x, g.y, lane);
    g = cs[19]; ry_lane<1>(v, g.x, g.y, lane);
    g = cs[20]; ry_lane<0>(v, g.x, g.y, lane);
    g = cs[21]; ry_reg<2>(v, g.x, g.y);
    g = cs[22]; ry_reg<1>(v, g.x, g.y);
    g = cs[23]; ry_reg<0>(v, g.x, g.y);
    g = cs[24]; crx_rr<0, 1>(v, g.x, g.y);
    g = cs[25]; crx_lr<4, 0>(v, g.x, g.y, lane);
    g = cs[26]; crx_ll<3, 4>(v, g.x, g.y, lane);
    g = cs[27]; crx_ll<2, 3>(v, g.x, g.y, lane);
    g = cs[28]; crx_ll<1, 2>(v, g.x, g.y, lane);
    g = cs[29]; crx_ll<0, 1>(v, g.x, g.y, lane);
    g = cs[30]; crx_rl<2, 0>(v, g.x, g.y);
    g = cs[31]; crx_rr<1, 2>(v, g.x, g.y);
}

/* --------- kernel 1: wparams (4 threads per dot; 2048 warps) ------------- */
__global__ void __launch_bounds__(256) k_wparams(const int* __restrict__ x,
                                                 const float* __restrict__ embW,
                                                 const float* __restrict__ e2rW,
                                                 const float* __restrict__ e2rb) {
    int bw = blockIdx.x, tid = threadIdx.x;
    __shared__ float emb[EMB];
    __shared__ int tok_s;
    if (tid == 0) tok_s = x[bw];
    __syncthreads();
    if (tid < 128)
        reinterpret_cast<float4*>(emb)[tid] =
            reinterpret_cast<const float4*>(embW + (size_t)tok_s * EMB)[tid];
    __syncthreads();

    int r = tid >> 2, part = tid & 3;            /* 4 threads per rot */
    const float4* wr = reinterpret_cast<const float4*>(e2rW + (size_t)r * EMB) + part * 32;
    const float4* es = reinterpret_cast<const float4*>(emb) + part * 32;
    float acc = 0.f;
#pragma unroll 8
    for (int j = 0; j < 32; j++) {
        float4 a = __ldg(&wr[j]);
        float4 b = es[j];
        acc += a.x * b.x + a.y * b.y + a.z * b.z + a.w * b.w;
    }
    acc += __shfl_down_sync(0xffffffffu, acc, 1);
    acc += __shfl_down_sync(0xffffffffu, acc, 2);
    if (part == 0) {
        float p = acc + e2rb[r];
        g_cs[bw * NROTS + r] = make_float2(cosf(0.5f * p), sinf(0.5f * p));
    }
}

/* --------- kernel 2: mega (sim 3 degrees + finalize + measure + FF1) ----- */
__global__ void __launch_bounds__(512) k_mega(
    const float* __restrict__ poly,
    const float* __restrict__ mix,
    const float* __restrict__ qff,
    const float* __restrict__ ff1W,
    const float* __restrict__ ff1b)
{
    int b = blockIdx.x, tid = threadIdx.x;
    int w = tid >> 5, lane = tid & 31;

    __shared__ float2 st_sh[NW * DIM];   /* 32 KB */
    __shared__ float2 cs_sh[NW * NROTS]; /* 8 KB */
    __shared__ float2 work[DIM];
    __shared__ float2 acc[DIM];
    __shared__ float2 coeffs[NW];
    __shared__ float2 csf[32];
    __shared__ float  red[8];
    __shared__ float  ex[NM];
    __shared__ float  inv_nrm_sh;

    for (int i = tid; i < NW * NROTS; i += 512)
        cs_sh[i] = g_cs[b * NW * NROTS + i];
    if (tid == 0) {
        float ssum = 0.f;
        for (int k = 0; k < NW; k++) {
            float re = mix[2 * k], im = mix[2 * k + 1];
            ssum += sqrtf(re * re + im * im);
        }
        float inv = 1.0f / fmaxf(ssum, 1e-12f);
        for (int k = 0; k < NW; k++)
            coeffs[k] = make_float2(mix[2 * k] * inv, mix[2 * k + 1] * inv);
    }
    if (tid < 32) {
        float p = qff[tid];
        csf[tid] = make_float2(cosf(0.5f * p), sinf(0.5f * p));
    }
    float p0 = poly[0], p1 = poly[1], p2 = poly[2], p3 = poly[3];
    if (tid < DIM) {
        bool z = (tid == 0);
        work[tid] = z ? make_float2(1.f, 0.f) : make_float2(0.f, 0.f);
        acc[tid]  = z ? make_float2(p0, 0.f)  : make_float2(0.f, 0.f);
    }
    __syncthreads();

#pragma unroll 1
    for (int d = 1; d <= 3; d++) {
        float pd = (d == 1) ? p1 : ((d == 2) ? p2 : p3);
        float2 v[8];
#pragma unroll
        for (int r = 0; r < 8; r++) v[r] = work[lane * 8 + r];

        sim_layer(v, cs_sh + w * NROTS, lane);
        sim_layer(v, cs_sh + w * NROTS + 32, lane);

#pragma unroll
        for (int r = 0; r < 8; r++) st_sh[w * DIM + lane * 8 + r] = v[r];
        __syncthreads();

        if (tid < DIM) {
            float2 s = make_float2(0.f, 0.f);
#pragma unroll
            for (int w2 = 0; w2 < NW; w2++) {
                float2 cw = coeffs[w2];
                float2 u  = st_sh[w2 * DIM + tid];
                s.x += cw.x * u.x - cw.y * u.y;
                s.y += cw.x * u.y + cw.y * u.x;
            }
            work[tid] = s;
            float2 a = acc[tid];
            a.x += pd * s.x; a.y += pd * s.y;
            acc[tid] = a;
        }
        __syncthreads();
    }

    /* normalize */
    float psum = fabsf(p0) + fabsf(p1) + fabsf(p2) + fabsf(p3);
    float inv1 = 1.0f / psum;
    float2 a2 = make_float2(0.f, 0.f);
    float nv = 0.f;
    if (tid < DIM) {
        a2 = acc[tid];
        a2.x *= inv1; a2.y *= inv1;
        nv = a2.x * a2.x + a2.y * a2.y;
    }
    for (int off = 16; off; off >>= 1) nv += __shfl_xor_sync(0xffffffffu, nv, off);
    if (tid < DIM && lane == 0) red[w] = nv;
    __syncthreads();
    if (tid == 0) {
        float s = 0.f;
        for (int k = 0; k < 8; k++) s += red[k];
        float nm = sqrtf(s);
        g_fp[b] = nm;
        inv_nrm_sh = 1.0f / fmaxf(nm, 1e-12f);
    }
    __syncthreads();
    float inv2 = inv_nrm_sh;
    if (tid < DIM) st_sh[tid] = make_float2(a2.x * inv2, a2.y * inv2);
    __syncthreads();

    /* final 32-gate circuit + measurement: warp 0 only */
    if (w == 0) {
        float2 v[8];
#pragma unroll
        for (int r = 0; r < 8; r++) v[r] = st_sh[lane * 8 + r];
        sim_layer(v, csf, lane);

        for (int q = 0; q < NQ; q++) {
            int bp = 7 - q;
            float cre = 0.f, cim = 0.f, zz = 0.f;
            if (bp >= 3) {
                int lb = bp - 3;
                int tb = (lane >> lb) & 1;
#pragma unroll
                for (int r = 0; r < 8; r++) {
                    float2 p = shfl_xor_f2(v[r], 1 << lb);
                    float nn = v[r].x * v[r].x + v[r].y * v[r].y;
                    if (tb == 0) {
                        cre += v[r].x * p.x + v[r].y * p.y;
                        cim += v[r].x * p.y - v[r].y * p.x;
                        zz  += nn;
                    } else {
                        zz  -= nn;
                    }
                }
            } else {
#pragma unroll
                for (int r0 = 0; r0 < 8; r0++) {
                    if (r0 & (1 << bp)) continue;
                    int r1 = r0 | (1 << bp);
                    cre += v[r0].x * v[r1].x + v[r0].y * v[r1].y;
                    cim += v[r0].x * v[r1].y - v[r0].y * v[r1].x;
                    zz  += v[r0].x * v[r0].x + v[r0].y * v[r0].y
                         - v[r1].x * v[r1].x - v[r1].y * v[r1].y;
                }
            }
            for (int off = 16; off; off >>= 1) {
                cre += __shfl_xor_sync(0xffffffffu, cre, off);
                cim += __shfl_xor_sync(0xffffffffu, cim, off);
                zz  += __shfl_xor_sync(0xffffffffu, zz, off);
            }
            if (lane == 0) { ex[q] = 2.f * cre; ex[8 + q] = 2.f * cim; ex[16 + q] = zz; }
        }
    }
    __syncthreads();

    /* FF1 + ReLU */
    {
        float s = ff1b[tid];
#pragma unroll
        for (int m = 0; m < NM; m++) s += ex[m] * ff1W[tid * NM + m];
        g_h[b * EMB + tid] = fmaxf(s, 0.f);
    }
}

/* --------- kernel 3: FF2, batch-split for occupancy ---------------------- */
__global__ void __launch_bounds__(128) k_ff2(const float* __restrict__ ff2W,
                                             const float* __restrict__ ff2b,
                                             float* __restrict__ out,
                                             int write_mean) {
    int tid = threadIdx.x;
    if (blockIdx.x == 0 && tid == 0 && write_mean) {
        float s = 0.f;
        for (int b = 0; b < BATCH; b++) s += g_fp[b];
        out[(size_t)BATCH * VOCAB] = s * (1.0f / BATCH);
    }

    int half   = blockIdx.x & 1;             /* batches [half*8, half*8+8) */
    int rowblk = blockIdx.x >> 1;

    __shared__ ull hs2[256 * 8];             /* [kp][bb] packed h, 16 KB */
    for (int idx = tid; idx < 256 * 8; idx += 128) {
        int kp = idx >> 3, bb = idx & 7;
        float2 hv = *reinterpret_cast<const float2*>(
            &g_h[(half * 8 + bb) * EMB + 2 * kp]);
        reinterpret_cast<float2*>(hs2)[idx] = hv;
    }
    __syncthreads();

    int v = rowblk * 128 + tid;
    bool ok = v < VOCAB;
    const ulonglong2* wp =
        reinterpret_cast<const ulonglong2*>(ff2W + (size_t)(ok ? v : 0) * EMB);

    ull acc[8];
#pragma unroll
    for (int bb = 0; bb < 8; bb++) acc[bb] = 0ull;

#pragma unroll 1
    for (int kb = 0; kb < 128; kb += 4) {
        ulonglong2 wv0 = wp[kb + 0];
        ulonglong2 wv1 = wp[kb + 1];
        ulonglong2 wv2 = wp[kb + 2];
        ulonglong2 wv3 = wp[kb + 3];
#pragma unroll
        for (int u = 0; u < 4; u++) {
            ulonglong2 wv = (u == 0) ? wv0 : (u == 1) ? wv1 : (u == 2) ? wv2 : wv3;
            const ull* h0 = &hs2[(2 * (kb + u)) * 8];
            const ull* h1 = h0 + 8;
#pragma unroll
            for (int bb = 0; bb < 8; bb += 2) {
                ulonglong2 hb0 = *reinterpret_cast<const ulonglong2*>(h0 + bb);
                ulonglong2 hb1 = *reinterpret_cast<const ulonglong2*>(h1 + bb);
                acc[bb]     = fma2(wv.x, hb0.x, acc[bb]);
                acc[bb + 1] = fma2(wv.x, hb0.y, acc[bb + 1]);
                acc[bb]     = fma2(wv.y, hb1.x, acc[bb]);
                acc[bb + 1] = fma2(wv.y, hb1.y, acc[bb + 1]);
            }
        }
    }

    if (ok) {
        float bias = ff2b[v];
#pragma unroll
        for (int bb = 0; bb < 8; bb++) {
            float2 p = upk2(acc[bb]);
            out[(size_t)(half * 8 + bb) * VOCAB + v] = p.x + p.y + bias;
        }
    }
}

/* ---------------- launch ------------------------------------------------- */
extern "C" void kernel_launch(void* const* d_in, const int* in_sizes, int n_in,
                              void* d_out, int out_size) {
    const int*   x    = (const int*)  d_in[0];
    const float* embW = (const float*)d_in[1];
    const float* e2rW = (const float*)d_in[2];
    const float* e2rb = (const float*)d_in[3];
    const float* poly = (const float*)d_in[4];
    const float* mix  = (const float*)d_in[5];
    const float* qff  = (const float*)d_in[6];
    const float* ff1W = (const float*)d_in[7];
    const float* ff1b = (const float*)d_in[8];
    const float* ff2W = (const float*)d_in[9];
    const float* ff2b = (const float*)d_in[10];
    float* out = (float*)d_out;

    int write_mean = (out_size > BATCH * VOCAB) ? 1 : 0;

    k_wparams<<<BATCH * NW, 256>>>(x, embW, e2rW, e2rb);
    k_mega<<<BATCH, 512>>>(poly, mix, qff, ff1W, ff1b);
    int rowblks = (VOCAB + 127) / 128;
    k_ff2<<<2 * rowblks, 128>>>(ff2W, ff2b, out, write_mean);
}

// round 10
// speedup vs baseline: 1.2595x; 1.2595x over previous
#include <cuda_runtime.h>
#include <cstdint>

#define NQ     8
#define DIM    256
#define NW     16
#define BATCH  16
#define NROTS  64
#define EMB    512
#define VOCAB  50257
#define NM     24

typedef unsigned long long ull;

/* ---------------- scratch (device globals) ------------------------------- */
__device__ float  g_fp[BATCH];
__device__ float  g_h[BATCH * EMB];
__device__ float2 g_cs[BATCH * NW * NROTS];   /* cos/sin of wparams */

/* ---------------- packed f32x2 helpers ----------------------------------- */
__device__ __forceinline__ ull fma2(ull a, ull b, ull c) {
    ull d;
    asm("fma.rn.f32x2 %0, %1, %2, %3;" : "=l"(d) : "l"(a), "l"(b), "l"(c));
    return d;
}
__device__ __forceinline__ float2 upk2(ull v) {
    float lo, hi;
    asm("mov.b64 {%0, %1}, %2;" : "=f"(lo), "=f"(hi) : "l"(v));
    return make_float2(lo, hi);
}
__device__ __forceinline__ ull pack2(float x, float y) {
    ull r;
    asm("mov.b64 %0, {%1, %2};" : "=l"(r) : "f"(x), "f"(y));
    return r;
}

/* ============ warp-level statevector gates (amp i = lane*8 + r) ========== */
__device__ __forceinline__ float2 shfl_xor_f2(float2 v, int m) {
    float2 r;
    r.x = __shfl_xor_sync(0xffffffffu, v.x, m);
    r.y = __shfl_xor_sync(0xffffffffu, v.y, m);
    return r;
}

template<int BP>
__device__ __forceinline__ void ry_reg(float2* v, float c, float s) {
#pragma unroll
    for (int r0 = 0; r0 < 8; r0++) {
        if (r0 & (1 << BP)) continue;
        const int r1 = r0 | (1 << BP);
        float2 a0 = v[r0], a1 = v[r1];
        v[r0] = make_float2(c * a0.x - s * a1.x, c * a0.y - s * a1.y);
        v[r1] = make_float2(s * a0.x + c * a1.x, s * a0.y + c * a1.y);
    }
}
template<int LB>
__device__ __forceinline__ void ry_lane(float2* v, float c, float s, int lane) {
    float ss = ((lane >> LB) & 1) ? s : -s;
#pragma unroll
    for (int r = 0; r < 8; r++) {
        float2 p = shfl_xor_f2(v[r], 1 << LB);
        v[r].x = c * v[r].x + ss * p.x;
        v[r].y = c * v[r].y + ss * p.y;
    }
}
template<int BC, int BT>
__device__ __forceinline__ void crx_rr(float2* v, float c, float s) {
#pragma unroll
    for (int r0 = 0; r0 < 8; r0++) {
        if (!(r0 & (1 << BC)) || (r0 & (1 << BT))) continue;
        const int r1 = r0 | (1 << BT);
        float2 a0 = v[r0], a1 = v[r1];
        v[r0] = make_float2(c * a0.x + s * a1.y, c * a0.y - s * a1.x);
        v[r1] = make_float2(s * a0.y + c * a1.x, -s * a0.x + c * a1.y);
    }
}
template<int LC, int BT>
__device__ __forceinline__ void crx_lr(float2* v, float c, float s, int lane) {
    if ((lane >> LC) & 1) {
#pragma unroll
        for (int r0 = 0; r0 < 8; r0++) {
            if (r0 & (1 << BT)) continue;
            const int r1 = r0 | (1 << BT);
            float2 a0 = v[r0], a1 = v[r1];
            v[r0] = make_float2(c * a0.x + s * a1.y, c * a0.y - s * a1.x);
            v[r1] = make_float2(s * a0.y + c * a1.x, -s * a0.x + c * a1.y);
        }
    }
}
template<int BC, int LT>
__device__ __forceinline__ void crx_rl(float2* v, float c, float s) {
#pragma unroll
    for (int r = 0; r < 8; r++) {
        if (!(r & (1 << BC))) continue;
        float2 p = shfl_xor_f2(v[r], 1 << LT);
        float2 a = v[r];
        v[r].x = c * a.x + s * p.y;
        v[r].y = c * a.y - s * p.x;
    }
}
template<int LC, int LT>
__device__ __forceinline__ void crx_ll(float2* v, float c, float s, int lane) {
    bool act = (lane >> LC) & 1;
#pragma unroll
    for (int r = 0; r < 8; r++) {
        float2 p = shfl_xor_f2(v[r], 1 << LT);
        if (act) {
            float2 a = v[r];
            v[r].x = c * a.x + s * p.y;
            v[r].y = c * a.y - s * p.x;
        }
    }
}

__device__ __forceinline__ void sim_layer(float2* v, const float2* cs, int lane) {
    float2 g;
    g = cs[0];  ry_lane<4>(v, g.x, g.y, lane);
    g = cs[1];  ry_lane<3>(v, g.x, g.y, lane);
    g = cs[2];  ry_lane<2>(v, g.x, g.y, lane);
    g = cs[3];  ry_lane<1>(v, g.x, g.y, lane);
    g = cs[4];  ry_lane<0>(v, g.x, g.y, lane);
    g = cs[5];  ry_reg<2>(v, g.x, g.y);
    g = cs[6];  ry_reg<1>(v, g.x, g.y);
    g = cs[7];  ry_reg<0>(v, g.x, g.y);
    g = cs[8];  crx_rl<0, 4>(v, g.x, g.y);
    g = cs[9];  crx_rr<1, 0>(v, g.x, g.y);
    g = cs[10]; crx_rr<2, 1>(v, g.x, g.y);
    g = cs[11]; crx_lr<0, 2>(v, g.x, g.y, lane);
    g = cs[12]; crx_ll<1, 0>(v, g.x, g.y, lane);
    g = cs[13]; crx_ll<2, 1>(v, g.x, g.y, lane);
    g = cs[14]; crx_ll<3, 2>(v, g.x, g.y, lane);
    g = cs[15]; crx_ll<4, 3>(v, g.x, g.y, lane);
    g = cs[16]; ry_lane<4>(v, g.x, g.y, lane);
    g = cs[17]; ry_lane<3>(v, g.x, g.y, lane);
    g = cs[18]; ry_lane<2>(v, g.x, g.y, lane);
    g = cs[19]; ry_lane<1>(v, g.x, g.y, lane);
    g = cs[20]; ry_lane<0>(v, g.x, g.y, lane);
    g = cs[21]; ry_reg<2>(v, g.x, g.y);
    g = cs[22]; ry_reg<1>(v, g.x, g.y);
    g = cs[23]; ry_reg<0>(v, g.x, g.y);
    g = cs[24]; crx_rr<0, 1>(v, g.x, g.y);
    g = cs[25]; crx_lr<4, 0>(v, g.x, g.y, lane);
    g = cs[26]; crx_ll<3, 4>(v, g.x, g.y, lane);
    g = cs[27]; crx_ll<2, 3>(v, g.x, g.y, lane);
    g = cs[28]; crx_ll<1, 2>(v, g.x, g.y, lane);
    g = cs[29]; crx_ll<0, 1>(v, g.x, g.y, lane);
    g = cs[30]; crx_rl<2, 0>(v, g.x, g.y);
    g = cs[31]; crx_rr<1, 2>(v, g.x, g.y);
}

/* --------- kernel 1: wparams, warp-per-rot coalesced GEMV ---------------- */
__global__ void __launch_bounds__(256) k_wparams(const int* __restrict__ x,
                                                 const float* __restrict__ embW,
                                                 const float* __restrict__ e2rW,
                                                 const float* __restrict__ e2rb) {
    int bw = blockIdx.x, tid = threadIdx.x;
    int w = tid >> 5, lane = tid & 31;
    __shared__ float emb[EMB];
    __shared__ int tok_s;
    if (tid == 0) tok_s = x[bw];
    __syncthreads();
    if (tid < 128)
        reinterpret_cast<float4*>(emb)[tid] =
            reinterpret_cast<const float4*>(embW + (size_t)tok_s * EMB)[tid];
    __syncthreads();

#pragma unroll
    for (int j = 0; j < 8; j++) {
        int r = w * 8 + j;
        const float4* wr = reinterpret_cast<const float4*>(e2rW + (size_t)r * EMB);
        const float4* es = reinterpret_cast<const float4*>(emb);
        float acc = 0.f;
#pragma unroll
        for (int i = 0; i < 4; i++) {
            float4 a = __ldg(&wr[lane + 32 * i]);
            float4 b = es[lane + 32 * i];
            acc += a.x * b.x + a.y * b.y + a.z * b.z + a.w * b.w;
        }
#pragma unroll
        for (int off = 16; off; off >>= 1)
            acc += __shfl_xor_sync(0xffffffffu, acc, off);
        if (lane == 0) {
            float p = acc + e2rb[r];
            g_cs[bw * NROTS + r] = make_float2(cosf(0.5f * p), sinf(0.5f * p));
        }
    }
}

/* --------- kernel 2: mega (sim 3 degrees + finalize + measure + FF1) ----- */
__global__ void __launch_bounds__(512) k_mega(
    const float* __restrict__ poly,
    const float* __restrict__ mix,
    const float* __restrict__ qff,
    const float* __restrict__ ff1W,
    const float* __restrict__ ff1b)
{
    int b = blockIdx.x, tid = threadIdx.x;
    int w = tid >> 5, lane = tid & 31;

    __shared__ float2 st_sh[NW * DIM];
    __shared__ float2 cs_sh[NW * NROTS];
    __shared__ float2 work[DIM];
    __shared__ float2 acc[DIM];
    __shared__ float2 coeffs[NW];
    __shared__ float2 csf[32];
    __shared__ float  red[8];
    __shared__ float  ex[NM];
    __shared__ float  inv_nrm_sh;

    for (int i = tid; i < NW * NROTS; i += 512)
        cs_sh[i] = g_cs[b * NW * NROTS + i];
    if (tid == 0) {
        float ssum = 0.f;
        for (int k = 0; k < NW; k++) {
            float re = mix[2 * k], im = mix[2 * k + 1];
            ssum += sqrtf(re * re + im * im);
        }
        float inv = 1.0f / fmaxf(ssum, 1e-12f);
        for (int k = 0; k < NW; k++)
            coeffs[k] = make_float2(mix[2 * k] * inv, mix[2 * k + 1] * inv);
    }
    if (tid < 32) {
        float p = qff[tid];
        csf[tid] = make_float2(cosf(0.5f * p), sinf(0.5f * p));
    }
    float p0 = poly[0], p1 = poly[1], p2 = poly[2], p3 = poly[3];
    if (tid < DIM) {
        bool z = (tid == 0);
        work[tid] = z ? make_float2(1.f, 0.f) : make_float2(0.f, 0.f);
        acc[tid]  = z ? make_float2(p0, 0.f)  : make_float2(0.f, 0.f);
    }
    __syncthreads();

#pragma unroll 1
    for (int d = 1; d <= 3; d++) {
        float pd = (d == 1) ? p1 : ((d == 2) ? p2 : p3);
        float2 v[8];
#pragma unroll
        for (int r = 0; r < 8; r++) v[r] = work[lane * 8 + r];

        sim_layer(v, cs_sh + w * NROTS, lane);
        sim_layer(v, cs_sh + w * NROTS + 32, lane);

#pragma unroll
        for (int r = 0; r < 8; r++) st_sh[w * DIM + lane * 8 + r] = v[r];
        __syncthreads();

        if (tid < DIM) {
            float2 s = make_float2(0.f, 0.f);
#pragma unroll
            for (int w2 = 0; w2 < NW; w2++) {
                float2 cw = coeffs[w2];
                float2 u  = st_sh[w2 * DIM + tid];
                s.x += cw.x * u.x - cw.y * u.y;
                s.y += cw.x * u.y + cw.y * u.x;
            }
            work[tid] = s;
            float2 a = acc[tid];
            a.x += pd * s.x; a.y += pd * s.y;
            acc[tid] = a;
        }
        __syncthreads();
    }

    /* normalize */
    float psum = fabsf(p0) + fabsf(p1) + fabsf(p2) + fabsf(p3);
    float inv1 = 1.0f / psum;
    float2 a2 = make_float2(0.f, 0.f);
    float nv = 0.f;
    if (tid < DIM) {
        a2 = acc[tid];
        a2.x *= inv1; a2.y *= inv1;
        nv = a2.x * a2.x + a2.y * a2.y;
    }
    for (int off = 16; off; off >>= 1) nv += __shfl_xor_sync(0xffffffffu, nv, off);
    if (tid < DIM && lane == 0) red[w] = nv;
    __syncthreads();
    if (tid == 0) {
        float s = 0.f;
        for (int k = 0; k < 8; k++) s += red[k];
        float nm = sqrtf(s);
        g_fp[b] = nm;
        inv_nrm_sh = 1.0f / fmaxf(nm, 1e-12f);
    }
    __syncthreads();
    float inv2 = inv_nrm_sh;
    if (tid < DIM) st_sh[tid] = make_float2(a2.x * inv2, a2.y * inv2);
    __syncthreads();

    /* final 32-gate circuit + measurement: warp 0 only */
    if (w == 0) {
        float2 v[8];
#pragma unroll
        for (int r = 0; r < 8; r++) v[r] = st_sh[lane * 8 + r];
        sim_layer(v, csf, lane);

        for (int q = 0; q < NQ; q++) {
            int bp = 7 - q;
            float cre = 0.f, cim = 0.f, zz = 0.f;
            if (bp >= 3) {
                int lb = bp - 3;
                int tb = (lane >> lb) & 1;
#pragma unroll
                for (int r = 0; r < 8; r++) {
                    float2 p = shfl_xor_f2(v[r], 1 << lb);
                    float nn = v[r].x * v[r].x + v[r].y * v[r].y;
                    if (tb == 0) {
                        cre += v[r].x * p.x + v[r].y * p.y;
                        cim += v[r].x * p.y - v[r].y * p.x;
                        zz  += nn;
                    } else {
                        zz  -= nn;
                    }
                }
            } else {
#pragma unroll
                for (int r0 = 0; r0 < 8; r0++) {
                    if (r0 & (1 << bp)) continue;
                    int r1 = r0 | (1 << bp);
                    cre += v[r0].x * v[r1].x + v[r0].y * v[r1].y;
                    cim += v[r0].x * v[r1].y - v[r0].y * v[r1].x;
                    zz  += v[r0].x * v[r0].x + v[r0].y * v[r0].y
                         - v[r1].x * v[r1].x - v[r1].y * v[r1].y;
                }
            }
            for (int off = 16; off; off >>= 1) {
                cre += __shfl_xor_sync(0xffffffffu, cre, off);
                cim += __shfl_xor_sync(0xffffffffu, cim, off);
                zz  += __shfl_xor_sync(0xffffffffu, zz, off);
            }
            if (lane == 0) { ex[q] = 2.f * cre; ex[8 + q] = 2.f * cim; ex[16 + q] = zz; }
        }
    }
    __syncthreads();

    /* FF1 + ReLU */
    {
        float s = ff1b[tid];
#pragma unroll
        for (int m = 0; m < NM; m++) s += ex[m] * ff1W[tid * NM + m];
        g_h[b * EMB + tid] = fmaxf(s, 0.f);
    }
}

/* --------- kernel 3: FF2 staged GEMM -------------------------------------
   block = 128 threads = 128 vocab rows. k in 16 chunks of 32 floats.
   W tile staged coalesced into swizzled smem (double-buffered), h resident
   in smem as [kpair][batch] ull (broadcast reads).
   dyn smem: hs[4096] ull (32 KB) | tile[2][2048] ull (32 KB) = 64 KB      */
__global__ void __launch_bounds__(128) k_ff2(const float* __restrict__ ff2W,
                                             const float* __restrict__ ff2b,
                                             float* __restrict__ out,
                                             int write_mean) {
    extern __shared__ ull sm[];
    ull* hs   = sm;            /* [kp*16 + b] = (h[b][2kp], h[b][2kp+1]) */
    ull* tile = sm + 4096;     /* 2 bufs × 16 kp × 128 rows (swizzled)   */

    int t = threadIdx.x;
    if (blockIdx.x == 0 && t == 0 && write_mean) {
        float s = 0.f;
        for (int b = 0; b < BATCH; b++) s += g_fp[b];
        out[(size_t)BATCH * VOCAB] = s * (1.0f / BATCH);
    }

    /* stage h: b fastest so STS is conflict-free */
    for (int idx = t; idx < 256 * 16; idx += 128) {
        int b = idx & 15, kp = idx >> 4;
        float2 hv = *reinterpret_cast<const float2*>(&g_h[b * EMB + 2 * kp]);
        hs[kp * 16 + b] = pack2(hv.x, hv.y);
    }

    int rowbase = blockIdx.x * 128;
    int v = rowbase + t;
    bool ok = v < VOCAB;

    /* per-thread staging mapping: idx = t + 128*i -> (row = idx>>3, c4 = idx&7) */
    float4 ld[8];
    const float4* Wf4 = reinterpret_cast<const float4*>(ff2W);

#define FF2_LOAD(c)                                                            \
    {                                                                          \
        _Pragma("unroll")                                                      \
        for (int i = 0; i < 8; i++) {                                          \
            int idx = t + 128 * i;                                             \
            int row = idx >> 3, c4 = idx & 7;                                  \
            int gr = rowbase + row;                                            \
            if (gr >= VOCAB) gr = VOCAB - 1;                                   \
            ld[i] = __ldg(&Wf4[(size_t)gr * 128 + (c) * 8 + c4]);              \
        }                                                                      \
    }
#define FF2_STORE(buf)                                                         \
    {                                                                          \
        ull* tb = tile + (buf) * 2048;                                         \
        _Pragma("unroll")                                                      \
        for (int i = 0; i < 8; i++) {                                          \
            int idx = t + 128 * i;                                             \
            int row = idx >> 3, kp2 = (idx & 7) * 2;                           \
            tb[kp2 * 128 + (row ^ kp2)]             = pack2(ld[i].x, ld[i].y); \
            tb[(kp2 + 1) * 128 + (row ^ (kp2 + 1))] = pack2(ld[i].z, ld[i].w); \
        }                                                                      \
    }

    ull acc[16];
#pragma unroll
    for (int b = 0; b < 16; b++) acc[b] = 0ull;

    FF2_LOAD(0);
    FF2_STORE(0);
    __syncthreads();

    int buf = 0;
#pragma unroll 1
    for (int c = 0; c < 16; c++) {
        if (c < 15) FF2_LOAD(c + 1);

        const ull* tb = tile + buf * 2048;
        const ull* hp = hs + c * 16 * 16;
#pragma unroll
        for (int kp2 = 0; kp2 < 16; kp2++) {
            ull wv = tb[kp2 * 128 + (t ^ kp2)];
            const ull* hq = hp + kp2 * 16;
#pragma unroll
            for (int b = 0; b < 16; b += 2) {
                ulonglong2 hb = *reinterpret_cast<const ulonglong2*>(hq + b);
                acc[b]     = fma2(wv, hb.x, acc[b]);
                acc[b + 1] = fma2(wv, hb.y, acc[b + 1]);
            }
        }

        if (c < 15) {
            FF2_STORE(buf ^ 1);
            __syncthreads();
            buf ^= 1;
        }
    }

    if (ok) {
        float bias = ff2b[v];
#pragma unroll
        for (int b = 0; b < 16; b++) {
            float2 p = upk2(acc[b]);
            out[(size_t)b * VOCAB + v] = p.x + p.y + bias;
        }
    }
#undef FF2_LOAD
#undef FF2_STORE
}

/* ---------------- launch ------------------------------------------------- */
extern "C" void kernel_launch(void* const* d_in, const int* in_sizes, int n_in,
                              void* d_out, int out_size) {
    const int*   x    = (const int*)  d_in[0];
    const float* embW = (const float*)d_in[1];
    const float* e2rW = (const float*)d_in[2];
    const float* e2rb = (const float*)d_in[3];
    const float* poly = (const float*)d_in[4];
    const float* mix  = (const float*)d_in[5];
    const float* qff  = (const float*)d_in[6];
    const float* ff1W = (const float*)d_in[7];
    const float* ff1b = (const float*)d_in[8];
    const float* ff2W = (const float*)d_in[9];
    const float* ff2b = (const float*)d_in[10];
    float* out = (float*)d_out;

    int write_mean = (out_size > BATCH * VOCAB) ? 1 : 0;

    cudaFuncSetAttribute(k_ff2, cudaFuncAttributeMaxDynamicSharedMemorySize,
                         64 * 1024);

    k_wparams<<<BATCH * NW, 256>>>(x, embW, e2rW, e2rb);
    k_mega<<<BATCH, 512>>>(poly, mix, qff, ff1W, ff1b);
    int blocks = (VOCAB + 127) / 128;
    k_ff2<<<blocks, 128, 64 * 1024>>>(ff2W, ff2b, out, write_mean);
}